// round 12
// baseline (speedup 1.0000x reference)
#include <cuda_runtime.h>
#include <cstdint>

#define NS 65536
#define D  32
#define R  128

typedef unsigned long long ull;

// pre-duplicated coefficient tables, [d][r] records:
//   gWV: (w, w, v, v) 16B    gCC: (c, c) 8B
__device__ float gWV[D * R * 4];
__device__ float gCC[D * R * 2];
__device__ float gBias[R];

__global__ void anfis_precomp(const float* __restrict__ a,
                              const float* __restrict__ b,
                              const float* __restrict__ c) {
    int r = blockIdx.x, d = threadIdx.x;
    float av = a[r * D + d];
    float bv = fmaxf(b[r * D + d], 1e-8f);
    float w  = 0.70710678118654752f / bv;
    float v  = -w * av;
    float cv = c[r * (D + 1) + d];
    int idx  = d * R + r;
    gWV[idx * 4 + 0] = w;
    gWV[idx * 4 + 1] = w;
    gWV[idx * 4 + 2] = v;
    gWV[idx * 4 + 3] = v;
    gCC[idx * 2 + 0] = cv;
    gCC[idx * 2 + 1] = cv;
    if (d == 0) gBias[r] = c[r * (D + 1) + D];
}

__device__ __forceinline__ ull fma2(ull a, ull b, ull c) {
    ull d;
    asm("fma.rn.f32x2 %0, %1, %2, %3;" : "=l"(d) : "l"(a), "l"(b), "l"(c));
    return d;
}
__device__ __forceinline__ ull add2(ull a, ull b) {
    ull d;
    asm("add.rn.f32x2 %0, %1, %2;" : "=l"(d) : "l"(a), "l"(b));
    return d;
}
__device__ __forceinline__ ull mul2(ull a, ull b) {
    ull d;
    asm("mul.rn.f32x2 %0, %1, %2;" : "=l"(d) : "l"(a), "l"(b));
    return d;
}
#define LDG128I(ptr, imm, lo, hi) \
    asm volatile("ld.global.nc.v2.u64 {%0, %1}, [%2 + %3];" \
                 : "=l"(lo), "=l"(hi) : "l"(ptr), "n"(imm))
#define LDG64I(ptr, imm, v) \
    asm volatile("ld.global.nc.u64 %0, [%1 + %2];" \
                 : "=l"(v) : "l"(ptr), "n"(imm))
#define LDS128I(base, imm, lo, hi) \
    asm volatile("ld.shared.v2.u64 {%0, %1}, [%2 + %3];" \
                 : "=l"(lo), "=l"(hi) : "r"(base), "n"(imm))
__device__ __forceinline__ void sts128(uint32_t addr, ull lo, ull hi) {
    asm volatile("st.shared.v2.u64 [%0], {%1, %2};" :: "r"(addr), "l"(lo), "l"(hi));
}
__device__ __forceinline__ void unpack2(ull v, float& lo, float& hi) {
    asm("mov.b64 {%0, %1}, %2;" : "=f"(lo), "=f"(hi) : "l"(v));
}
__device__ __forceinline__ ull pack2(float lo, float hi) {
    ull v;
    asm("mov.b64 %0, {%1, %2};" : "=l"(v) : "f"(lo), "f"(hi));
    return v;
}
__device__ __forceinline__ ull shfl2(ull v, int off) {
    return __shfl_xor_sync(0xffffffffu, v, off);
}

// smem: xt[32][16] f32 (2048B) + red[8 pairs][4 warps][16B] (512B)
#define OFF_RED 2048

// pairs 2i, 2i+1 at dim d: 1 broadcast LDS.128 + 6 fma2
#define XS(d, i, AGa, ALa, AGb, ALb)                                          \
    {                                                                         \
        ull xa, xc, u;                                                        \
        LDS128I(xB, (d) * 64 + (i) * 16, xa, xc);                             \
        u = fma2(ww, xa, vv); AGa = fma2(u, u, AGa); ALa = fma2(cc, xa, ALa); \
        u = fma2(ww, xc, vv); AGb = fma2(u, u, AGb); ALb = fma2(cc, xc, ALb); \
    }
// one d: 1 LDG.128 + 1 LDG.64 + 4 LDS.128 + 24 fma2, all immediates
#define STEPD(d)                                                              \
    {                                                                         \
        ull ww, vv, cc;                                                       \
        LDG128I(wvp, (d) * 2048, ww, vv);                                     \
        LDG64I(ccp, (d) * 1024, cc);                                          \
        XS(d, 0, ag0, al0, ag1, al1)                                          \
        XS(d, 1, ag2, al2, ag3, al3)                                          \
        XS(d, 2, ag4, al4, ag5, al5)                                          \
        XS(d, 3, ag6, al6, ag7, al7)                                          \
    }

#define EPI(p, AG, AL)                                                        \
    {                                                                         \
        float e0, e1;                                                         \
        unpack2(AG, e0, e1);                                                  \
        float s0 = __expf(-e0), s1 = __expf(-e1);                             \
        ull s2 = pack2(s0, s1);                                               \
        strengths[(n0 + 2 * (p))     * R + r] = s0;                           \
        strengths[(n0 + 2 * (p) + 1) * R + r] = s1;                           \
        ull pp2 = mul2(s2, add2(AL, bias2));                                  \
        ull ss2 = s2;                                                         \
        _Pragma("unroll")                                                     \
        for (int off = 16; off > 0; off >>= 1) {                              \
            ss2 = add2(ss2, shfl2(ss2, off));                                 \
            pp2 = add2(pp2, shfl2(pp2, off));                                 \
        }                                                                     \
        if (lane == 0) sts128(redB + (p) * 64 + q * 16, ss2, pp2);            \
        AG = s2;                                                              \
    }

#define FIN(p, AG)                                                            \
    {                                                                         \
        ull s01, p01, s23, p23, s45, p45, s67, p67;                           \
        LDS128I(redB, (p) * 64 + 0,  s01, p01);                               \
        LDS128I(redB, (p) * 64 + 16, s23, p23);                               \
        LDS128I(redB, (p) * 64 + 32, s45, p45);                               \
        LDS128I(redB, (p) * 64 + 48, s67, p67);                               \
        ull sst = add2(add2(s01, s23), add2(s45, s67));                       \
        ull ppt = add2(add2(p01, p23), add2(p45, p67));                       \
        float ta, tb;                                                         \
        unpack2(sst, ta, tb);                                                 \
        float inva = 1.0f / (ta + 1e-8f);                                     \
        float invb = 1.0f / (tb + 1e-8f);                                     \
        float s0, s1;                                                         \
        unpack2(AG, s0, s1);                                                  \
        normalized[(n0 + 2 * (p))     * R + r] = s0 * inva;                   \
        normalized[(n0 + 2 * (p) + 1) * R + r] = s1 * invb;                   \
        if (q == 0 && lane == 0) {                                            \
            float pa, pb;                                                     \
            unpack2(ppt, pa, pb);                                             \
            pred[n0 + 2 * (p)]     = pa * inva;                               \
            pred[n0 + 2 * (p) + 1] = pb * invb;                               \
        }                                                                     \
    }

__global__ void __launch_bounds__(128, 8)
anfis_main(const float* __restrict__ X,
           float* __restrict__ pred,
           float* __restrict__ strengths,
           float* __restrict__ normalized) {
    __shared__ float smem[(2048 + 512) / 4];
    uint32_t sbase;
    {
        uint64_t t;
        asm("cvta.to.shared.u64 %0, %1;" : "=l"(t) : "l"(smem));
        sbase = (uint32_t)t;
    }

    const int n0 = blockIdx.x * 16;     // 16 samples per block

    // stage X transposed: xt[dim][sample]; 128 threads, one float4 each
    {
        int row = threadIdx.x >> 3;     // sample 0..15
        int seg = threadIdx.x & 7;      // float4 along D
        float4 v = *reinterpret_cast<const float4*>(X + (n0 + row) * D + seg * 4);
        smem[(seg * 4 + 0) * 16 + row] = v.x;
        smem[(seg * 4 + 1) * 16 + row] = v.y;
        smem[(seg * 4 + 2) * 16 + row] = v.z;
        smem[(seg * 4 + 3) * 16 + row] = v.w;
    }
    __syncthreads();

    const int lane = threadIdx.x & 31;
    const int q    = threadIdx.x >> 5;   // warp = rule quarter
    const int r    = q * 32 + lane;      // this lane's rule

    const float* wvp = gWV + r * 4;      // 16B record, d stride 2048B
    const float* ccp = gCC + r * 2;      // 8B record,  d stride 1024B
    const uint32_t xB   = sbase;
    const uint32_t redB = sbase + OFF_RED;

    ull ag0 = 0, ag1 = 0, ag2 = 0, ag3 = 0, ag4 = 0, ag5 = 0, ag6 = 0, ag7 = 0;
    ull al0 = 0, al1 = 0, al2 = 0, al3 = 0, al4 = 0, al5 = 0, al6 = 0, al7 = 0;

    STEPD(0)  STEPD(1)  STEPD(2)  STEPD(3)  STEPD(4)  STEPD(5)  STEPD(6)  STEPD(7)
    STEPD(8)  STEPD(9)  STEPD(10) STEPD(11) STEPD(12) STEPD(13) STEPD(14) STEPD(15)
    STEPD(16) STEPD(17) STEPD(18) STEPD(19) STEPD(20) STEPD(21) STEPD(22) STEPD(23)
    STEPD(24) STEPD(25) STEPD(26) STEPD(27) STEPD(28) STEPD(29) STEPD(30) STEPD(31)

    float biasf;
    asm volatile("ld.global.nc.f32 %0, [%1];" : "=f"(biasf) : "l"(gBias + r));
    const ull bias2 = pack2(biasf, biasf);

    EPI(0, ag0, al0) EPI(1, ag1, al1) EPI(2, ag2, al2) EPI(3, ag3, al3)
    EPI(4, ag4, al4) EPI(5, ag5, al5) EPI(6, ag6, al6) EPI(7, ag7, al7)
    __syncthreads();
    FIN(0, ag0) FIN(1, ag1) FIN(2, ag2) FIN(3, ag3)
    FIN(4, ag4) FIN(5, ag5) FIN(6, ag6) FIN(7, ag7)
}

extern "C" void kernel_launch(void* const* d_in, const int* in_sizes, int n_in,
                              void* d_out, int out_size) {
    const float* X = (const float*)d_in[0];
    const float* a = (const float*)d_in[1];
    const float* b = (const float*)d_in[2];
    const float* c = (const float*)d_in[3];

    float* out        = (float*)d_out;
    float* pred       = out;
    float* strengths  = out + NS;
    float* normalized = out + NS + NS * R;

    anfis_precomp<<<R, D>>>(a, b, c);
    anfis_main<<<NS / 16, 128>>>(X, pred, strengths, normalized);
}

// round 13
// speedup vs baseline: 1.5656x; 1.5656x over previous
#include <cuda_runtime.h>
#include <cstdint>

#define NS 65536
#define D  32
#define R  128

typedef unsigned long long ull;

// gWV2: interleaved (w, v) float2 records, [d][r] -> 8B, d-stride 1024B
// gC:   scalar c transposed [d][r]           -> 4B, d-stride 512B
__device__ float gWV2[D * R * 2];
__device__ float gC[D * R];
__device__ float gBias[R];

__global__ void anfis_precomp(const float* __restrict__ a,
                              const float* __restrict__ b,
                              const float* __restrict__ c) {
    int r = blockIdx.x, d = threadIdx.x;
    float av = a[r * D + d];
    float bv = fmaxf(b[r * D + d], 1e-8f);
    float w  = 0.70710678118654752f / bv;
    gWV2[(d * R + r) * 2 + 0] = w;
    gWV2[(d * R + r) * 2 + 1] = -w * av;
    gC[d * R + r] = c[r * (D + 1) + d];
    if (d == 0) gBias[r] = c[r * (D + 1) + D];
}

__device__ __forceinline__ ull fma2(ull a, ull b, ull c) {
    ull d;
    asm("fma.rn.f32x2 %0, %1, %2, %3;" : "=l"(d) : "l"(a), "l"(b), "l"(c));
    return d;
}
__device__ __forceinline__ ull add2(ull a, ull b) {
    ull d;
    asm("add.rn.f32x2 %0, %1, %2;" : "=l"(d) : "l"(a), "l"(b));
    return d;
}
__device__ __forceinline__ ull mul2(ull a, ull b) {
    ull d;
    asm("mul.rn.f32x2 %0, %1, %2;" : "=l"(d) : "l"(a), "l"(b));
    return d;
}
#define LDG64I(ptr, imm, v) \
    asm volatile("ld.global.nc.u64 %0, [%1 + %2];" : "=l"(v) : "l"(ptr), "n"(imm))
#define LDGF(ptr, imm, f) \
    asm volatile("ld.global.nc.f32 %0, [%1 + %2];" : "=f"(f) : "l"(ptr), "n"(imm))
#define LDS128I(base, imm, lo, hi) \
    asm volatile("ld.shared.v2.u64 {%0, %1}, [%2 + %3];" \
                 : "=l"(lo), "=l"(hi) : "r"(base), "n"(imm))
__device__ __forceinline__ void sts128(uint32_t addr, ull lo, ull hi) {
    asm volatile("st.shared.v2.u64 [%0], {%1, %2};" :: "r"(addr), "l"(lo), "l"(hi));
}
__device__ __forceinline__ void unpack2(ull v, float& lo, float& hi) {
    asm("mov.b64 {%0, %1}, %2;" : "=f"(lo), "=f"(hi) : "l"(v));
}
__device__ __forceinline__ ull pack2(float lo, float hi) {
    ull v;
    asm("mov.b64 %0, {%1, %2};" : "=l"(v) : "f"(lo), "f"(hi));
    return v;
}
__device__ __forceinline__ ull shfl2(ull v, int off) {
    return __shfl_xor_sync(0xffffffffu, v, off);
}

// smem: xt[32][8] f32 (1024B) + red[4 pairs][4 warps][16B] (256B)
#define OFF_RED 1024

// one d: 1 LDG.64 + 1 LDG.32 + 2 broadcast LDS.128 + 12 fma2
#define STEPD(d)                                                              \
    {                                                                         \
        ull wv;                                                               \
        float w, v, cc;                                                       \
        LDG64I(wvp, (d) * 1024, wv);                                          \
        LDGF(cp, (d) * 512, cc);                                              \
        unpack2(wv, w, v);                                                    \
        ull w2 = pack2(w, w), v2 = pack2(v, v), c2 = pack2(cc, cc);           \
        ull x0, x1, x2, x3, u;                                                \
        LDS128I(xB, (d) * 32,      x0, x1);                                   \
        LDS128I(xB, (d) * 32 + 16, x2, x3);                                   \
        u = fma2(w2, x0, v2); ag0 = fma2(u, u, ag0); al0 = fma2(c2, x0, al0); \
        u = fma2(w2, x1, v2); ag1 = fma2(u, u, ag1); al1 = fma2(c2, x1, al1); \
        u = fma2(w2, x2, v2); ag2 = fma2(u, u, ag2); al2 = fma2(c2, x2, al2); \
        u = fma2(w2, x3, v2); ag3 = fma2(u, u, ag3); al3 = fma2(c2, x3, al3); \
    }

#define EPI(p, AG, AL)                                                        \
    {                                                                         \
        float e0, e1;                                                         \
        unpack2(AG, e0, e1);                                                  \
        float s0 = __expf(-e0), s1 = __expf(-e1);                             \
        ull s2 = pack2(s0, s1);                                               \
        strengths[(n0 + 2 * (p))     * R + r] = s0;                           \
        strengths[(n0 + 2 * (p) + 1) * R + r] = s1;                           \
        ull pp2 = mul2(s2, add2(AL, bias2));                                  \
        ull ss2 = s2;                                                         \
        _Pragma("unroll")                                                     \
        for (int off = 16; off > 0; off >>= 1) {                              \
            ss2 = add2(ss2, shfl2(ss2, off));                                 \
            pp2 = add2(pp2, shfl2(pp2, off));                                 \
        }                                                                     \
        if (lane == 0) sts128(redB + (p) * 64 + q * 16, ss2, pp2);            \
        AG = s2;                                                              \
    }

#define FIN(p, AG)                                                            \
    {                                                                         \
        ull s01, p01, s23, p23, s45, p45, s67, p67;                           \
        LDS128I(redB, (p) * 64 + 0,  s01, p01);                               \
        LDS128I(redB, (p) * 64 + 16, s23, p23);                               \
        LDS128I(redB, (p) * 64 + 32, s45, p45);                               \
        LDS128I(redB, (p) * 64 + 48, s67, p67);                               \
        ull sst = add2(add2(s01, s23), add2(s45, s67));                       \
        ull ppt = add2(add2(p01, p23), add2(p45, p67));                       \
        float ta, tb;                                                         \
        unpack2(sst, ta, tb);                                                 \
        float inva = 1.0f / (ta + 1e-8f);                                     \
        float invb = 1.0f / (tb + 1e-8f);                                     \
        float s0, s1;                                                         \
        unpack2(AG, s0, s1);                                                  \
        normalized[(n0 + 2 * (p))     * R + r] = s0 * inva;                   \
        normalized[(n0 + 2 * (p) + 1) * R + r] = s1 * invb;                   \
        if (q == 0 && lane == 0) {                                            \
            float pa, pb;                                                     \
            unpack2(ppt, pa, pb);                                             \
            pred[n0 + 2 * (p)]     = pa * inva;                               \
            pred[n0 + 2 * (p) + 1] = pb * invb;                               \
        }                                                                     \
    }

__global__ void __launch_bounds__(128, 10)
anfis_main(const float* __restrict__ X,
           float* __restrict__ pred,
           float* __restrict__ strengths,
           float* __restrict__ normalized) {
    __shared__ float smem[(1024 + 256) / 4 + 32];
    uint32_t sbase;
    {
        uint64_t t;
        asm("cvta.to.shared.u64 %0, %1;" : "=l"(t) : "l"(smem));
        sbase = (uint32_t)t;
    }

    const int n0 = blockIdx.x * 8;      // 8 samples per block

    // stage X transposed: xt[d][s], 64 threads one float4 each
    if (threadIdx.x < 64) {
        int row = threadIdx.x >> 3;     // 0..7
        int seg = threadIdx.x & 7;      // 0..7
        float4 v = *reinterpret_cast<const float4*>(X + (n0 + row) * D + seg * 4);
        smem[(seg * 4 + 0) * 8 + row] = v.x;
        smem[(seg * 4 + 1) * 8 + row] = v.y;
        smem[(seg * 4 + 2) * 8 + row] = v.z;
        smem[(seg * 4 + 3) * 8 + row] = v.w;
    }
    __syncthreads();

    const int lane = threadIdx.x & 31;
    const int q    = threadIdx.x >> 5;   // warp = rule quarter
    const int r    = q * 32 + lane;      // this lane's rule

    const float* wvp = gWV2 + r * 2;     // 8B record, d-stride 1024B
    const float* cp  = gC + r;           // 4B, d-stride 512B
    const uint32_t xB   = sbase;
    const uint32_t redB = sbase + OFF_RED;

    ull ag0 = 0, ag1 = 0, ag2 = 0, ag3 = 0;
    ull al0 = 0, al1 = 0, al2 = 0, al3 = 0;

    STEPD(0)  STEPD(1)  STEPD(2)  STEPD(3)  STEPD(4)  STEPD(5)  STEPD(6)  STEPD(7)
    STEPD(8)  STEPD(9)  STEPD(10) STEPD(11) STEPD(12) STEPD(13) STEPD(14) STEPD(15)
    STEPD(16) STEPD(17) STEPD(18) STEPD(19) STEPD(20) STEPD(21) STEPD(22) STEPD(23)
    STEPD(24) STEPD(25) STEPD(26) STEPD(27) STEPD(28) STEPD(29) STEPD(30) STEPD(31)

    float biasf;
    asm volatile("ld.global.nc.f32 %0, [%1];" : "=f"(biasf) : "l"(gBias + r));
    const ull bias2 = pack2(biasf, biasf);

    EPI(0, ag0, al0) EPI(1, ag1, al1) EPI(2, ag2, al2) EPI(3, ag3, al3)
    __syncthreads();
    FIN(0, ag0) FIN(1, ag1) FIN(2, ag2) FIN(3, ag3)
}

extern "C" void kernel_launch(void* const* d_in, const int* in_sizes, int n_in,
                              void* d_out, int out_size) {
    const float* X = (const float*)d_in[0];
    const float* a = (const float*)d_in[1];
    const float* b = (const float*)d_in[2];
    const float* c = (const float*)d_in[3];

    float* out        = (float*)d_out;
    float* pred       = out;
    float* strengths  = out + NS;
    float* normalized = out + NS + NS * R;

    anfis_precomp<<<R, D>>>(a, b, c);
    anfis_main<<<NS / 8, 128>>>(X, pred, strengths, normalized);
}